// round 4
// baseline (speedup 1.0000x reference)
#include <cuda_runtime.h>
#include <math.h>

// Problem constants
#define B_  4
#define L_  4096
#define E_  512
#define H_  16
#define D_  32
#define ML  (B_*L_)            // 16384 tokens
#define EPS_ 1e-6f

// ---------------------------------------------------------------------------
// Scratch (static __device__ arrays; no allocation anywhere)
// ---------------------------------------------------------------------------
__device__ float g_Q[ML*E_];   // elu(q)+1
__device__ float g_K[ML*E_];   // elu(k)+1
__device__ float g_V[ML*E_];   // v projection (unscaled; /L * L cancels exactly)
__device__ float g_M[ML*E_];   // message

#define NCHUNK 8
#define KV_ELEMS   (B_*H_*D_*D_)     // 65536
#define KSUM_ELEMS (B_*H_*D_)        // 2048
#define PART_STRIDE (KV_ELEMS + KSUM_ELEMS)   // 67584
__device__ float g_part[NCHUNK * PART_STRIDE];
__device__ float g_KV[KV_ELEMS];
__device__ float g_Ksum[KSUM_ELEMS];

// ---------------------------------------------------------------------------
// Packed f32x2 helpers (FFMA2: 2x fp32 FMA throughput vs FFMA-3reg on sm_103a)
// ---------------------------------------------------------------------------
__device__ __forceinline__ unsigned long long pk2(float lo, float hi) {
    unsigned long long r;
    asm("mov.b64 %0, {%1, %2};" : "=l"(r) : "f"(lo), "f"(hi));
    return r;
}
__device__ __forceinline__ unsigned long long ffma2(unsigned long long a,
                                                    unsigned long long b,
                                                    unsigned long long c) {
    unsigned long long d;
    asm("fma.rn.f32x2 %0, %1, %2, %3;" : "=l"(d) : "l"(a), "l"(b), "l"(c));
    return d;
}
__device__ __forceinline__ float2 upk2(unsigned long long v) {
    float2 f;
    asm("mov.b64 {%0, %1}, %2;" : "=f"(f.x), "=f"(f.y) : "l"(v));
    return f;
}

// ---------------------------------------------------------------------------
// GEMM: C[M,N] = A[M,K] @ W[N,K]^T  with M=16384, N=K=512 (all 4 GEMMs).
// Block tile 128x128xBK16, 256 threads, 8x8 per-thread micro-tile (split as
// 2x2 of 4x4 at offsets {0,64} for conflict-free LDS.128), FFMA2 inner loop,
// register prefetch of the next k-tile. Optional fused elu+1 epilogue.
// z = blockIdx.z selects one of up to 3 (A,W,C) triples; bit z of actmask
// enables the elu+1 epilogue for that triple.
// ---------------------------------------------------------------------------
__global__ __launch_bounds__(256, 2)
void gemm_xwt(const float* __restrict__ A0, const float* __restrict__ A1,
              const float* __restrict__ A2,
              const float* __restrict__ W0, const float* __restrict__ W1,
              const float* __restrict__ W2,
              float* __restrict__ C0, float* __restrict__ C1,
              float* __restrict__ C2,
              int actmask)
{
    const int z = blockIdx.z;
    const float* A = (z == 0) ? A0 : (z == 1 ? A1 : A2);
    const float* W = (z == 0) ? W0 : (z == 1 ? W1 : W2);
    float*       C = (z == 0) ? C0 : (z == 1 ? C1 : C2);
    const bool act = (actmask >> z) & 1;

    __shared__ float As[16][128];
    __shared__ float Bs[16][128];

    const int tid = threadIdx.x;
    const int tx  = tid & 15;          // 0..15 -> N micro-position
    const int ty  = tid >> 4;          // 0..15 -> M micro-position
    const int m0  = blockIdx.y * 128;
    const int n0  = blockIdx.x * 128;

    // global-load mapping: 512 float4 per tile per operand, 2 per thread
    const int lr = tid >> 2;           // row 0..63 (second half at +64)
    const int lk = (tid & 3) << 2;     // k offset 0,4,8,12

    const float* Ap = A + (m0 + lr) * 512 + lk;
    const float* Wp = W + (n0 + lr) * 512 + lk;

    unsigned long long acc[8][4];
    #pragma unroll
    for (int i = 0; i < 8; i++)
        #pragma unroll
        for (int j = 0; j < 4; j++) acc[i][j] = 0ULL;

    // ---- prologue: load k-tile 0 and stage to smem ----
    float4 ra0 = *(const float4*)(Ap);
    float4 ra1 = *(const float4*)(Ap + 64 * 512);
    float4 rb0 = *(const float4*)(Wp);
    float4 rb1 = *(const float4*)(Wp + 64 * 512);

    As[lk + 0][lr]      = ra0.x; As[lk + 1][lr]      = ra0.y;
    As[lk + 2][lr]      = ra0.z; As[lk + 3][lr]      = ra0.w;
    As[lk + 0][lr + 64] = ra1.x; As[lk + 1][lr + 64] = ra1.y;
    As[lk + 2][lr + 64] = ra1.z; As[lk + 3][lr + 64] = ra1.w;
    Bs[lk + 0][lr]      = rb0.x; Bs[lk + 1][lr]      = rb0.y;
    Bs[lk + 2][lr]      = rb0.z; Bs[lk + 3][lr]      = rb0.w;
    Bs[lk + 0][lr + 64] = rb1.x; Bs[lk + 1][lr + 64] = rb1.y;
    Bs[lk + 2][lr + 64] = rb1.z; Bs[lk + 3][lr + 64] = rb1.w;
    __syncthreads();

    for (int kt = 0; kt < 32; ++kt) {
        // prefetch next k-tile into registers (overlaps with compute)
        if (kt < 31) {
            const float* Ap2 = Ap + (kt + 1) * 16;
            const float* Wp2 = Wp + (kt + 1) * 16;
            ra0 = *(const float4*)(Ap2);
            ra1 = *(const float4*)(Ap2 + 64 * 512);
            rb0 = *(const float4*)(Wp2);
            rb1 = *(const float4*)(Wp2 + 64 * 512);
        }

        #pragma unroll
        for (int k = 0; k < 16; k++) {
            float4 a0 = *(const float4*)&As[k][ty << 2];
            float4 a1 = *(const float4*)&As[k][64 + (ty << 2)];
            float4 b0 = *(const float4*)&Bs[k][tx << 2];
            float4 b1 = *(const float4*)&Bs[k][64 + (tx << 2)];

            unsigned long long bb0 = pk2(b0.x, b0.y);
            unsigned long long bb1 = pk2(b0.z, b0.w);
            unsigned long long bb2 = pk2(b1.x, b1.y);
            unsigned long long bb3 = pk2(b1.z, b1.w);

            float av[8] = {a0.x, a0.y, a0.z, a0.w, a1.x, a1.y, a1.z, a1.w};
            #pragma unroll
            for (int i = 0; i < 8; i++) {
                unsigned long long aa = pk2(av[i], av[i]);
                acc[i][0] = ffma2(aa, bb0, acc[i][0]);
                acc[i][1] = ffma2(aa, bb1, acc[i][1]);
                acc[i][2] = ffma2(aa, bb2, acc[i][2]);
                acc[i][3] = ffma2(aa, bb3, acc[i][3]);
            }
        }

        if (kt < 31) {
            __syncthreads();
            As[lk + 0][lr]      = ra0.x; As[lk + 1][lr]      = ra0.y;
            As[lk + 2][lr]      = ra0.z; As[lk + 3][lr]      = ra0.w;
            As[lk + 0][lr + 64] = ra1.x; As[lk + 1][lr + 64] = ra1.y;
            As[lk + 2][lr + 64] = ra1.z; As[lk + 3][lr + 64] = ra1.w;
            Bs[lk + 0][lr]      = rb0.x; Bs[lk + 1][lr]      = rb0.y;
            Bs[lk + 2][lr]      = rb0.z; Bs[lk + 3][lr]      = rb0.w;
            Bs[lk + 0][lr + 64] = rb1.x; Bs[lk + 1][lr + 64] = rb1.y;
            Bs[lk + 2][lr + 64] = rb1.z; Bs[lk + 3][lr + 64] = rb1.w;
            __syncthreads();
        }
    }

    // ---- epilogue: unpack, optional elu(x)+1 (= x+1 if x>0 else exp(x)) ----
    #pragma unroll
    for (int i = 0; i < 8; i++) {
        const int m = m0 + ((i < 4) ? (ty * 4 + i) : (64 + ty * 4 + (i - 4)));
        float2 p0 = upk2(acc[i][0]);
        float2 p1 = upk2(acc[i][1]);
        float2 p2 = upk2(acc[i][2]);
        float2 p3 = upk2(acc[i][3]);
        float o[8] = {p0.x, p0.y, p1.x, p1.y, p2.x, p2.y, p3.x, p3.y};
        if (act) {
            #pragma unroll
            for (int j = 0; j < 8; j++)
                o[j] = (o[j] > 0.0f) ? (o[j] + 1.0f) : expf(o[j]);
        }
        *(float4*)(C + m * 512 + n0 + (tx << 2))      = make_float4(o[0], o[1], o[2], o[3]);
        *(float4*)(C + m * 512 + n0 + 64 + (tx << 2)) = make_float4(o[4], o[5], o[6], o[7]);
    }
}

// ---------------------------------------------------------------------------
// Stage 2a: per-(s-chunk, b, h) partial KV[d][dv] = sum_s K[s,d]*V[s,dv]
// and partial Ksum[d]. Deterministic (no float atomics): partials to g_part.
// grid (NCHUNK, B*H), 256 threads. Thread owns (d = tid>>3, dv quad).
// ---------------------------------------------------------------------------
__global__ void kv_partial(const float* __restrict__ Kf,
                           const float* __restrict__ Vf,
                           float* __restrict__ part)
{
    const int c  = blockIdx.x;
    const int bh = blockIdx.y;
    const int b  = bh >> 4;
    const int h  = bh & 15;
    const int tid = threadIdx.x;

    __shared__ float Ks[8][32];
    __shared__ float Vs[8][32];

    const int d   = tid >> 3;
    const int dv0 = (tid & 7) << 2;
    const int lr  = tid >> 5;   // 0..7
    const int lc  = tid & 31;

    const size_t base = ((size_t)(b * L_ + c * (L_ / NCHUNK)) * 512) + h * 32;
    const float* Kb = Kf + base;
    const float* Vb = Vf + base;

    float a0 = 0.f, a1 = 0.f, a2 = 0.f, a3 = 0.f, ks = 0.f;

    for (int s = 0; s < L_ / NCHUNK; s += 8) {
        Ks[lr][lc] = Kb[(size_t)(s + lr) * 512 + lc];
        Vs[lr][lc] = Vb[(size_t)(s + lr) * 512 + lc];
        __syncthreads();
        #pragma unroll
        for (int u = 0; u < 8; u++) {
            float kd = Ks[u][d];
            float4 vv = *(const float4*)&Vs[u][dv0];
            a0 += kd * vv.x; a1 += kd * vv.y;
            a2 += kd * vv.z; a3 += kd * vv.w;
            ks += kd;
        }
        __syncthreads();
    }

    float* p = part + (size_t)c * PART_STRIDE;
    const int o = bh * 1024 + d * 32 + dv0;
    p[o + 0] = a0; p[o + 1] = a1; p[o + 2] = a2; p[o + 3] = a3;
    if ((tid & 7) == 0) p[KV_ELEMS + bh * 32 + d] = ks;
}

// Stage 2b: reduce NCHUNK partials -> g_KV, g_Ksum (deterministic order)
__global__ void kv_reduce(const float* __restrict__ part,
                          float* __restrict__ KV,
                          float* __restrict__ Ksum)
{
    const int i = blockIdx.x * 256 + threadIdx.x;
    if (i >= PART_STRIDE) return;
    float s = 0.f;
    #pragma unroll
    for (int c = 0; c < NCHUNK; c++) s += part[(size_t)c * PART_STRIDE + i];
    if (i < KV_ELEMS) KV[i] = s;
    else              Ksum[i - KV_ELEMS] = s;
}

// ---------------------------------------------------------------------------
// Stage 3: message. Per block: 128 tokens x 1 head.
// Z = 1/(Q.Ksum + eps); msg[dv] = Z * sum_d Q[d]*KV[d][dv]
// Qs/Ms padded to stride 33 (bank-conflict-free); KV reads are broadcast.
// ---------------------------------------------------------------------------
__global__ void msg_kernel(const float* __restrict__ Qf,
                           const float* __restrict__ KV,
                           const float* __restrict__ Ksum,
                           float* __restrict__ Msg)
{
    const int l0 = blockIdx.x * 128;
    const int h  = blockIdx.y;
    const int b  = blockIdx.z;
    const int bh = b * 16 + h;
    const int tid = threadIdx.x;

    __shared__ float Qs[128 * 33];
    __shared__ float Ms[128 * 33];
    __shared__ float KVs[1024];
    __shared__ float ks[32];

    const float* Qb = Qf + ((size_t)(b * L_ + l0) * 512) + h * 32;
    for (int i = tid; i < 128 * 32; i += 128) {
        int l = i >> 5, d = i & 31;
        Qs[l * 33 + d] = Qb[(size_t)l * 512 + d];
    }
    for (int i = tid; i < 1024; i += 128) KVs[i] = KV[(size_t)bh * 1024 + i];
    if (tid < 32) ks[tid] = Ksum[bh * 32 + tid];
    __syncthreads();

    // cache my Q row in registers
    float qr[32];
    #pragma unroll
    for (int d = 0; d < 32; d++) qr[d] = Qs[tid * 33 + d];

    float zden = 0.f;
    #pragma unroll
    for (int d = 0; d < 32; d++) zden += qr[d] * ks[d];
    const float z = 1.0f / (zden + EPS_);

    #pragma unroll 4
    for (int dv = 0; dv < 32; dv++) {
        float m = 0.f;
        #pragma unroll
        for (int d = 0; d < 32; d++) m += qr[d] * KVs[d * 32 + dv];
        Ms[tid * 33 + dv] = m * z;
    }
    __syncthreads();

    float* Mb = Msg + ((size_t)(b * L_ + l0) * 512) + h * 32;
    for (int i = tid; i < 128 * 32; i += 128) {
        int l = i >> 5, d = i & 31;
        Mb[(size_t)l * 512 + d] = Ms[l * 33 + d];
    }
}

// ---------------------------------------------------------------------------
// Launch. Inputs (metadata order): query, key, value, Wq, Wk, Wv, Wm. f32 out.
// ---------------------------------------------------------------------------
extern "C" void kernel_launch(void* const* d_in, const int* in_sizes, int n_in,
                              void* d_out, int out_size)
{
    (void)in_sizes; (void)n_in; (void)out_size;
    const float* q  = (const float*)d_in[0];
    const float* k  = (const float*)d_in[1];
    const float* v  = (const float*)d_in[2];
    const float* Wq = (const float*)d_in[3];
    const float* Wk = (const float*)d_in[4];
    const float* Wv = (const float*)d_in[5];
    const float* Wm = (const float*)d_in[6];
    float* out = (float*)d_out;

    float *gQ, *gK, *gV, *gM, *gPart, *gKV, *gKs;
    cudaGetSymbolAddress((void**)&gQ,    g_Q);
    cudaGetSymbolAddress((void**)&gK,    g_K);
    cudaGetSymbolAddress((void**)&gV,    g_V);
    cudaGetSymbolAddress((void**)&gM,    g_M);
    cudaGetSymbolAddress((void**)&gPart, g_part);
    cudaGetSymbolAddress((void**)&gKV,   g_KV);
    cudaGetSymbolAddress((void**)&gKs,   g_Ksum);

    // 1) fused projections: q,k -> elu+1 ; v -> raw (scaling cancels)
    gemm_xwt<<<dim3(4, 128, 3), 256>>>(q, k, v, Wq, Wk, Wv, gQ, gK, gV, 0x3);

    // 2) KV + Ksum (deterministic two-phase reduction)
    kv_partial<<<dim3(NCHUNK, B_ * H_), 256>>>(gK, gV, gPart);
    kv_reduce<<<(PART_STRIDE + 255) / 256, 256>>>(gPart, gKV, gKs);

    // 3) message
    msg_kernel<<<dim3(L_ / 128, H_, B_), 128>>>(gQ, gKV, gKs, gM);

    // 4) output merge projection
    gemm_xwt<<<dim3(4, 128, 1), 256>>>(gM, gM, gM, Wm, Wm, Wm, out, out, out, 0);
}

// round 5
// speedup vs baseline: 1.4967x; 1.4967x over previous
#include <cuda_runtime.h>
#include <cuda_bf16.h>
#include <math.h>

// Problem constants
#define B_  4
#define L_  4096
#define E_  512
#define H_  16
#define D_  32
#define ML  (B_*L_)            // 16384 tokens
#define EPS_ 1e-6f

// ---------------------------------------------------------------------------
// Scratch (static __device__ arrays; no allocation anywhere)
// ---------------------------------------------------------------------------
// bf16 hi/lo splits of GEMM inputs
__device__ __nv_bfloat16 g_qh[ML*E_], g_ql[ML*E_];
__device__ __nv_bfloat16 g_kh[ML*E_], g_kl[ML*E_];
__device__ __nv_bfloat16 g_vh[ML*E_], g_vl[ML*E_];
__device__ __nv_bfloat16 g_Mh[ML*E_], g_Ml[ML*E_];
__device__ __nv_bfloat16 g_Wh[4*E_*E_], g_Wl[4*E_*E_];
// fp32 intermediates for the (cheap) linear-attention core
__device__ float g_Q[ML*E_];   // elu(q)+1
__device__ float g_K[ML*E_];   // elu(k)+1
__device__ float g_V[ML*E_];   // v projection (unscaled; /L * L cancels exactly)

#define NCHUNK 8
#define KV_ELEMS   (B_*H_*D_*D_)     // 65536
#define KSUM_ELEMS (B_*H_*D_)        // 2048
#define PART_STRIDE (KV_ELEMS + KSUM_ELEMS)   // 67584
__device__ float g_part[NCHUNK * PART_STRIDE];
__device__ float g_KV[KV_ELEMS];
__device__ float g_Ksum[KSUM_ELEMS];

// ---------------------------------------------------------------------------
// PTX helpers: ldmatrix + bf16 mma (fp32 accumulate)
// ---------------------------------------------------------------------------
__device__ __forceinline__ unsigned smem_u32(const void* p) {
    return (unsigned)__cvta_generic_to_shared(p);
}
__device__ __forceinline__ void ldsm_x4(unsigned* r, unsigned addr) {
    asm volatile("ldmatrix.sync.aligned.m8n8.x4.shared.b16 {%0,%1,%2,%3}, [%4];"
                 : "=r"(r[0]), "=r"(r[1]), "=r"(r[2]), "=r"(r[3]) : "r"(addr));
}
__device__ __forceinline__ void mma_bf16(float* c, const unsigned* a, const unsigned* b) {
    asm volatile("mma.sync.aligned.m16n8k16.row.col.f32.bf16.bf16.f32 "
                 "{%0,%1,%2,%3}, {%4,%5,%6,%7}, {%8,%9}, {%0,%1,%2,%3};"
                 : "+f"(c[0]), "+f"(c[1]), "+f"(c[2]), "+f"(c[3])
                 : "r"(a[0]), "r"(a[1]), "r"(a[2]), "r"(a[3]),
                   "r"(b[0]), "r"(b[1]));
}

// ---------------------------------------------------------------------------
// fp32 -> (bf16 hi, bf16 lo) exact split, vectorized x4
// ---------------------------------------------------------------------------
__global__ void split_bf16(const float* __restrict__ x,
                           __nv_bfloat16* __restrict__ hi,
                           __nv_bfloat16* __restrict__ lo, int n)
{
    int i = (blockIdx.x * 256 + threadIdx.x) * 4;
    if (i >= n) return;
    float4 v = *(const float4*)(x + i);
    __nv_bfloat16 h0 = __float2bfloat16(v.x);
    __nv_bfloat16 h1 = __float2bfloat16(v.y);
    __nv_bfloat16 h2 = __float2bfloat16(v.z);
    __nv_bfloat16 h3 = __float2bfloat16(v.w);
    __nv_bfloat16 l0 = __float2bfloat16(v.x - __bfloat162float(h0));
    __nv_bfloat16 l1 = __float2bfloat16(v.y - __bfloat162float(h1));
    __nv_bfloat16 l2 = __float2bfloat16(v.z - __bfloat162float(h2));
    __nv_bfloat16 l3 = __float2bfloat16(v.w - __bfloat162float(h3));
    __nv_bfloat162* Hp = (__nv_bfloat162*)(hi + i);
    __nv_bfloat162* Lp = (__nv_bfloat162*)(lo + i);
    Hp[0] = __halves2bfloat162(h0, h1);
    Hp[1] = __halves2bfloat162(h2, h3);
    Lp[0] = __halves2bfloat162(l0, l1);
    Lp[1] = __halves2bfloat162(l2, l3);
}

// ---------------------------------------------------------------------------
// GEMM: C[M,N] = A[M,K] @ W[N,K]^T in bf16x3 split with fp32 accumulation.
//   C = Ahi*Whi + Ahi*Wlo + Alo*Whi    (lo*lo term ~2^-16, dropped)
// M=16384, N=K=512. Block tile 128x128, k-tile 32, 256 threads = 8 warps,
// warp tile 32x64 (2 m16-tiles x 8 n8-tiles), mma.m16n8k16.
// smem row stride 40 bf16 (80B = 20 banks) -> ldmatrix conflict-free.
// Register prefetch of next k-tile. Optional fused elu+1 epilogue (bit z of
// actmask). blockIdx.z picks one of up to 3 (A,W,C) triples.
// ---------------------------------------------------------------------------
struct GemmArgs {
    const __nv_bfloat16* Ah[3]; const __nv_bfloat16* Al[3];
    const __nv_bfloat16* Wh[3]; const __nv_bfloat16* Wl[3];
    float* C[3];
    int actmask;
};

__global__ __launch_bounds__(256)
void gemm_bf16x3(GemmArgs args)
{
    const int z = blockIdx.z;
    const __nv_bfloat16* Ah = args.Ah[z];
    const __nv_bfloat16* Al = args.Al[z];
    const __nv_bfloat16* Wh = args.Wh[z];
    const __nv_bfloat16* Wl = args.Wl[z];
    float* C = args.C[z];
    const bool act = (args.actmask >> z) & 1;

    __shared__ __nv_bfloat16 sAh[128 * 40];
    __shared__ __nv_bfloat16 sAl[128 * 40];
    __shared__ __nv_bfloat16 sBh[128 * 40];
    __shared__ __nv_bfloat16 sBl[128 * 40];

    const int tid  = threadIdx.x;
    const int lane = tid & 31;
    const int warp = tid >> 5;
    const int m0 = blockIdx.y * 128;
    const int n0 = blockIdx.x * 128;
    const int wm0 = (warp & 3) * 32;     // warp row origin in tile
    const int wn0 = (warp >> 2) * 64;    // warp col origin in tile

    // global load mapping: per thread 2 uint4 (16 bf16) per operand tile
    const int lrow = tid >> 2;           // 0..63 (second at +64)
    const int lkc  = (tid & 3) * 8;      // k offset 0,8,16,24

    const __nv_bfloat16* gAh0 = Ah + (size_t)(m0 + lrow) * 512 + lkc;
    const __nv_bfloat16* gAl0 = Al + (size_t)(m0 + lrow) * 512 + lkc;
    const __nv_bfloat16* gBh0 = Wh + (size_t)(n0 + lrow) * 512 + lkc;
    const __nv_bfloat16* gBl0 = Wl + (size_t)(n0 + lrow) * 512 + lkc;

    float acc[2][8][4];
    #pragma unroll
    for (int i = 0; i < 2; i++)
        #pragma unroll
        for (int j = 0; j < 8; j++)
            #pragma unroll
            for (int t = 0; t < 4; t++) acc[i][j][t] = 0.0f;

    // smem store offsets (bf16 elements)
    const int s0 = lrow * 40 + lkc;
    const int s1 = (lrow + 64) * 40 + lkc;

    // ---- prologue: k-tile 0 ----
    uint4 pah0 = *(const uint4*)(gAh0);
    uint4 pah1 = *(const uint4*)(gAh0 + 64 * 512);
    uint4 pal0 = *(const uint4*)(gAl0);
    uint4 pal1 = *(const uint4*)(gAl0 + 64 * 512);
    uint4 pbh0 = *(const uint4*)(gBh0);
    uint4 pbh1 = *(const uint4*)(gBh0 + 64 * 512);
    uint4 pbl0 = *(const uint4*)(gBl0);
    uint4 pbl1 = *(const uint4*)(gBl0 + 64 * 512);

    *(uint4*)&sAh[s0] = pah0; *(uint4*)&sAh[s1] = pah1;
    *(uint4*)&sAl[s0] = pal0; *(uint4*)&sAl[s1] = pal1;
    *(uint4*)&sBh[s0] = pbh0; *(uint4*)&sBh[s1] = pbh1;
    *(uint4*)&sBl[s0] = pbl0; *(uint4*)&sBl[s1] = pbl1;
    __syncthreads();

    // ldmatrix address components
    const int a_r = lane & 15;              // row within m16 tile
    const int a_c = (lane >> 4) * 8;        // col half
    const int b_r = lane & 7;               // row within n8 tile
    const int b_nt = (lane >> 4) & 1;       // which of 2 n-tiles in x4
    const int b_c = ((lane >> 3) & 1) * 8;  // col half

    for (int kt = 0; kt < 16; ++kt) {
        if (kt < 15) {
            const int ko = (kt + 1) * 32;
            pah0 = *(const uint4*)(gAh0 + ko);
            pah1 = *(const uint4*)(gAh0 + 64 * 512 + ko);
            pal0 = *(const uint4*)(gAl0 + ko);
            pal1 = *(const uint4*)(gAl0 + 64 * 512 + ko);
            pbh0 = *(const uint4*)(gBh0 + ko);
            pbh1 = *(const uint4*)(gBh0 + 64 * 512 + ko);
            pbl0 = *(const uint4*)(gBl0 + ko);
            pbl1 = *(const uint4*)(gBl0 + 64 * 512 + ko);
        }

        #pragma unroll
        for (int ks = 0; ks < 2; ks++) {
            const int kk = ks * 16;
            unsigned ah[2][4], al[2][4];
            ldsm_x4(ah[0], smem_u32(&sAh[(wm0 + a_r) * 40 + kk + a_c]));
            ldsm_x4(ah[1], smem_u32(&sAh[(wm0 + 16 + a_r) * 40 + kk + a_c]));
            ldsm_x4(al[0], smem_u32(&sAl[(wm0 + a_r) * 40 + kk + a_c]));
            ldsm_x4(al[1], smem_u32(&sAl[(wm0 + 16 + a_r) * 40 + kk + a_c]));

            #pragma unroll
            for (int ntp = 0; ntp < 4; ntp++) {
                unsigned bh[4], bl[4];
                const int brow = wn0 + ntp * 16 + b_nt * 8 + b_r;
                ldsm_x4(bh, smem_u32(&sBh[brow * 40 + kk + b_c]));
                ldsm_x4(bl, smem_u32(&sBl[brow * 40 + kk + b_c]));
                #pragma unroll
                for (int half = 0; half < 2; half++) {
                    const int nt = ntp * 2 + half;
                    const unsigned* bhp = bh + 2 * half;
                    const unsigned* blp = bl + 2 * half;
                    mma_bf16(acc[0][nt], ah[0], bhp);
                    mma_bf16(acc[0][nt], ah[0], blp);
                    mma_bf16(acc[0][nt], al[0], bhp);
                    mma_bf16(acc[1][nt], ah[1], bhp);
                    mma_bf16(acc[1][nt], ah[1], blp);
                    mma_bf16(acc[1][nt], al[1], bhp);
                }
            }
        }

        if (kt < 15) {
            __syncthreads();
            *(uint4*)&sAh[s0] = pah0; *(uint4*)&sAh[s1] = pah1;
            *(uint4*)&sAl[s0] = pal0; *(uint4*)&sAl[s1] = pal1;
            *(uint4*)&sBh[s0] = pbh0; *(uint4*)&sBh[s1] = pbh1;
            *(uint4*)&sBl[s0] = pbl0; *(uint4*)&sBl[s1] = pbl1;
            __syncthreads();
        }
    }

    // ---- epilogue: optional elu(x)+1 (= x+1 if x>0 else exp(x)), fp32 out ----
    const int row0 = m0 + wm0 + (lane >> 2);
    const int col0 = n0 + wn0 + (lane & 3) * 2;
    #pragma unroll
    for (int mt = 0; mt < 2; mt++) {
        #pragma unroll
        for (int nt = 0; nt < 8; nt++) {
            float c0 = acc[mt][nt][0], c1 = acc[mt][nt][1];
            float c2 = acc[mt][nt][2], c3 = acc[mt][nt][3];
            if (act) {
                c0 = (c0 > 0.0f) ? (c0 + 1.0f) : expf(c0);
                c1 = (c1 > 0.0f) ? (c1 + 1.0f) : expf(c1);
                c2 = (c2 > 0.0f) ? (c2 + 1.0f) : expf(c2);
                c3 = (c3 > 0.0f) ? (c3 + 1.0f) : expf(c3);
            }
            const int r = row0 + mt * 16;
            const int cc = col0 + nt * 8;
            *(float2*)(C + (size_t)r * 512 + cc)       = make_float2(c0, c1);
            *(float2*)(C + (size_t)(r + 8) * 512 + cc) = make_float2(c2, c3);
        }
    }
}

// ---------------------------------------------------------------------------
// Stage 2a: per-(s-chunk, b, h) partial KV[d][dv] = sum_s K[s,d]*V[s,dv]
// and partial Ksum[d]. Deterministic (no float atomics).
// ---------------------------------------------------------------------------
__global__ void kv_partial(const float* __restrict__ Kf,
                           const float* __restrict__ Vf,
                           float* __restrict__ part)
{
    const int c  = blockIdx.x;
    const int bh = blockIdx.y;
    const int b  = bh >> 4;
    const int h  = bh & 15;
    const int tid = threadIdx.x;

    __shared__ float Ks[8][32];
    __shared__ float Vs[8][32];

    const int d   = tid >> 3;
    const int dv0 = (tid & 7) << 2;
    const int lr  = tid >> 5;   // 0..7
    const int lc  = tid & 31;

    const size_t base = ((size_t)(b * L_ + c * (L_ / NCHUNK)) * 512) + h * 32;
    const float* Kb = Kf + base;
    const float* Vb = Vf + base;

    float a0 = 0.f, a1 = 0.f, a2 = 0.f, a3 = 0.f, ks = 0.f;

    for (int s = 0; s < L_ / NCHUNK; s += 8) {
        Ks[lr][lc] = Kb[(size_t)(s + lr) * 512 + lc];
        Vs[lr][lc] = Vb[(size_t)(s + lr) * 512 + lc];
        __syncthreads();
        #pragma unroll
        for (int u = 0; u < 8; u++) {
            float kd = Ks[u][d];
            float4 vv = *(const float4*)&Vs[u][dv0];
            a0 += kd * vv.x; a1 += kd * vv.y;
            a2 += kd * vv.z; a3 += kd * vv.w;
            ks += kd;
        }
        __syncthreads();
    }

    float* p = part + (size_t)c * PART_STRIDE;
    const int o = bh * 1024 + d * 32 + dv0;
    p[o + 0] = a0; p[o + 1] = a1; p[o + 2] = a2; p[o + 3] = a3;
    if ((tid & 7) == 0) p[KV_ELEMS + bh * 32 + d] = ks;
}

// Stage 2b: reduce NCHUNK partials -> g_KV, g_Ksum (deterministic order)
__global__ void kv_reduce(const float* __restrict__ part,
                          float* __restrict__ KV,
                          float* __restrict__ Ksum)
{
    const int i = blockIdx.x * 256 + threadIdx.x;
    if (i >= PART_STRIDE) return;
    float s = 0.f;
    #pragma unroll
    for (int c = 0; c < NCHUNK; c++) s += part[(size_t)c * PART_STRIDE + i];
    if (i < KV_ELEMS) KV[i] = s;
    else              Ksum[i - KV_ELEMS] = s;
}

// ---------------------------------------------------------------------------
// Stage 3: message. Per block: 128 tokens x 1 head.
// Z = 1/(Q.Ksum + eps); msg[dv] = Z * sum_d Q[d]*KV[d][dv]
// Emits message directly as bf16 hi/lo split for the merge GEMM.
// ---------------------------------------------------------------------------
__global__ void msg_kernel(const float* __restrict__ Qf,
                           const float* __restrict__ KV,
                           const float* __restrict__ Ksum,
                           __nv_bfloat16* __restrict__ Mh,
                           __nv_bfloat16* __restrict__ Ml)
{
    const int l0 = blockIdx.x * 128;
    const int h  = blockIdx.y;
    const int b  = blockIdx.z;
    const int bh = b * 16 + h;
    const int tid = threadIdx.x;

    __shared__ float Qs[128 * 33];
    __shared__ float Ms[128 * 33];
    __shared__ float KVs[1024];
    __shared__ float ks[32];

    const float* Qb = Qf + ((size_t)(b * L_ + l0) * 512) + h * 32;
    for (int i = tid; i < 128 * 32; i += 128) {
        int l = i >> 5, d = i & 31;
        Qs[l * 33 + d] = Qb[(size_t)l * 512 + d];
    }
    for (int i = tid; i < 1024; i += 128) KVs[i] = KV[(size_t)bh * 1024 + i];
    if (tid < 32) ks[tid] = Ksum[bh * 32 + tid];
    __syncthreads();

    float qr[32];
    #pragma unroll
    for (int d = 0; d < 32; d++) qr[d] = Qs[tid * 33 + d];

    float zden = 0.f;
    #pragma unroll
    for (int d = 0; d < 32; d++) zden += qr[d] * ks[d];
    const float z = 1.0f / (zden + EPS_);

    #pragma unroll 4
    for (int dv = 0; dv < 32; dv++) {
        float m = 0.f;
        #pragma unroll
        for (int d = 0; d < 32; d++) m += qr[d] * KVs[d * 32 + dv];
        Ms[tid * 33 + dv] = m * z;
    }
    __syncthreads();

    __nv_bfloat16* Mbh = Mh + ((size_t)(b * L_ + l0) * 512) + h * 32;
    __nv_bfloat16* Mbl = Ml + ((size_t)(b * L_ + l0) * 512) + h * 32;
    for (int i = tid; i < 128 * 32; i += 128) {
        int l = i >> 5, d = i & 31;
        float m = Ms[l * 33 + d];
        __nv_bfloat16 hi = __float2bfloat16(m);
        Mbh[(size_t)l * 512 + d] = hi;
        Mbl[(size_t)l * 512 + d] = __float2bfloat16(m - __bfloat162float(hi));
    }
}

// ---------------------------------------------------------------------------
// Launch. Inputs (metadata order): query, key, value, Wq, Wk, Wv, Wm. f32 out.
// ---------------------------------------------------------------------------
extern "C" void kernel_launch(void* const* d_in, const int* in_sizes, int n_in,
                              void* d_out, int out_size)
{
    (void)in_sizes; (void)n_in; (void)out_size;
    const float* q  = (const float*)d_in[0];
    const float* k  = (const float*)d_in[1];
    const float* v  = (const float*)d_in[2];
    const float* Wq = (const float*)d_in[3];
    const float* Wk = (const float*)d_in[4];
    const float* Wv = (const float*)d_in[5];
    const float* Wm = (const float*)d_in[6];
    float* out = (float*)d_out;

    __nv_bfloat16 *qh, *ql, *kh, *kl, *vh, *vl, *Mh, *Ml, *Whb, *Wlb;
    float *gQ, *gK, *gV, *gPart, *gKV, *gKs;
    cudaGetSymbolAddress((void**)&qh,  g_qh);
    cudaGetSymbolAddress((void**)&ql,  g_ql);
    cudaGetSymbolAddress((void**)&kh,  g_kh);
    cudaGetSymbolAddress((void**)&kl,  g_kl);
    cudaGetSymbolAddress((void**)&vh,  g_vh);
    cudaGetSymbolAddress((void**)&vl,  g_vl);
    cudaGetSymbolAddress((void**)&Mh,  g_Mh);
    cudaGetSymbolAddress((void**)&Ml,  g_Ml);
    cudaGetSymbolAddress((void**)&Whb, g_Wh);
    cudaGetSymbolAddress((void**)&Wlb, g_Wl);
    cudaGetSymbolAddress((void**)&gQ,    g_Q);
    cudaGetSymbolAddress((void**)&gK,    g_K);
    cudaGetSymbolAddress((void**)&gV,    g_V);
    cudaGetSymbolAddress((void**)&gPart, g_part);
    cudaGetSymbolAddress((void**)&gKV,   g_KV);
    cudaGetSymbolAddress((void**)&gKs,   g_Ksum);

    const int EE = E_ * E_;

    // 0) exact fp32 -> bf16 hi/lo splits
    const int nA = ML * E_;
    split_bf16<<<nA / 4 / 256, 256>>>(q, qh, ql, nA);
    split_bf16<<<nA / 4 / 256, 256>>>(k, kh, kl, nA);
    split_bf16<<<nA / 4 / 256, 256>>>(v, vh, vl, nA);
    split_bf16<<<EE / 4 / 256, 256>>>(Wq, Whb + 0 * EE, Wlb + 0 * EE, EE);
    split_bf16<<<EE / 4 / 256, 256>>>(Wk, Whb + 1 * EE, Wlb + 1 * EE, EE);
    split_bf16<<<EE / 4 / 256, 256>>>(Wv, Whb + 2 * EE, Wlb + 2 * EE, EE);
    split_bf16<<<EE / 4 / 256, 256>>>(Wm, Whb + 3 * EE, Wlb + 3 * EE, EE);

    // 1) fused projections on tensor cores: q,k -> elu+1 ; v -> raw
    {
        GemmArgs a;
        a.Ah[0] = qh; a.Al[0] = ql; a.Wh[0] = Whb + 0 * EE; a.Wl[0] = Wlb + 0 * EE; a.C[0] = gQ;
        a.Ah[1] = kh; a.Al[1] = kl; a.Wh[1] = Whb + 1 * EE; a.Wl[1] = Wlb + 1 * EE; a.C[1] = gK;
        a.Ah[2] = vh; a.Al[2] = vl; a.Wh[2] = Whb + 2 * EE; a.Wl[2] = Wlb + 2 * EE; a.C[2] = gV;
        a.actmask = 0x3;
        gemm_bf16x3<<<dim3(4, 128, 3), 256>>>(a);
    }

    // 2) KV + Ksum (deterministic two-phase reduction)
    kv_partial<<<dim3(NCHUNK, B_ * H_), 256>>>(gK, gV, gPart);
    kv_reduce<<<(PART_STRIDE + 255) / 256, 256>>>(gPart, gKV, gKs);

    // 3) message (emits bf16 hi/lo directly)
    msg_kernel<<<dim3(L_ / 128, H_, B_), 128>>>(gQ, gKV, gKs, Mh, Ml);

    // 4) output merge projection on tensor cores
    {
        GemmArgs a;
        a.Ah[0] = Mh; a.Al[0] = Ml; a.Wh[0] = Whb + 3 * EE; a.Wl[0] = Wlb + 3 * EE; a.C[0] = out;
        a.Ah[1] = Mh; a.Al[1] = Ml; a.Wh[1] = Whb + 3 * EE; a.Wl[1] = Wlb + 3 * EE; a.C[1] = out;
        a.Ah[2] = Mh; a.Al[2] = Ml; a.Wh[2] = Whb + 3 * EE; a.Wl[2] = Wlb + 3 * EE; a.C[2] = out;
        a.actmask = 0;
        gemm_bf16x3<<<dim3(4, 128, 1), 256>>>(a);
    }
}

// round 7
// speedup vs baseline: 1.6260x; 1.0864x over previous
#include <cuda_runtime.h>
#include <cuda_bf16.h>
#include <math.h>
#include <stdint.h>

// Problem constants
#define B_  4
#define L_  4096
#define E_  512
#define H_  16
#define ML  (B_*L_)            // 16384 tokens
#define EPS_ 1e-6f

// ---------------------------------------------------------------------------
// Scratch (static __device__ arrays; no allocation anywhere)
// ---------------------------------------------------------------------------
__device__ float g_Q[ML*E_];   // elu(q)+1
__device__ float g_K[ML*E_];   // elu(k)+1
__device__ float g_V[ML*E_];   // v projection (unscaled; /L * L cancels exactly)
__device__ float g_M[ML*E_];   // message

#define NCHUNK 32
#define KV_ELEMS   (B_*H_*32*32)     // 65536
#define KSUM_ELEMS (B_*H_*32)        // 2048
#define PART_STRIDE (KV_ELEMS + KSUM_ELEMS)   // 67584
__device__ float g_part[NCHUNK * PART_STRIDE];
__device__ float g_KV[KV_ELEMS];
__device__ float g_Ksum[KSUM_ELEMS];

// ---------------------------------------------------------------------------
// PTX helpers: ldmatrix + bf16 mma (fp32 accumulate)
// ---------------------------------------------------------------------------
__device__ __forceinline__ unsigned smem_u32(const void* p) {
    return (unsigned)__cvta_generic_to_shared(p);
}
__device__ __forceinline__ void ldsm_x4(unsigned* r, unsigned addr) {
    asm volatile("ldmatrix.sync.aligned.m8n8.x4.shared.b16 {%0,%1,%2,%3}, [%4];"
                 : "=r"(r[0]), "=r"(r[1]), "=r"(r[2]), "=r"(r[3]) : "r"(addr));
}
__device__ __forceinline__ void mma_bf16(float* c, const unsigned* a, const unsigned* b) {
    asm volatile("mma.sync.aligned.m16n8k16.row.col.f32.bf16.bf16.f32 "
                 "{%0,%1,%2,%3}, {%4,%5,%6,%7}, {%8,%9}, {%0,%1,%2,%3};"
                 : "+f"(c[0]), "+f"(c[1]), "+f"(c[2]), "+f"(c[3])
                 : "r"(a[0]), "r"(a[1]), "r"(a[2]), "r"(a[3]),
                   "r"(b[0]), "r"(b[1]));
}

// ---------------------------------------------------------------------------
// 8 fp32 -> packed bf16 hi (truncation) + bf16 lo (exact residual, rn)
//   hi = bits & 0xFFFF0000 (round-toward-zero bf16); lo = x - hi (exact fp32)
//   a = hi + lo captures ~17 mantissa bits; 3-term mma gives ~2^-16 rel err.
// ---------------------------------------------------------------------------
__device__ __forceinline__ void cvt8(const float* __restrict__ v8,
                                     uint4& h, uint4& l) {
    uint32_t hp[4], lp[4];
    #pragma unroll
    for (int i = 0; i < 4; i++) {
        float x0 = v8[2*i], x1 = v8[2*i+1];
        uint32_t b0 = __float_as_uint(x0) & 0xFFFF0000u;
        uint32_t b1 = __float_as_uint(x1) & 0xFFFF0000u;
        hp[i] = (b0 >> 16) | b1;                 // bf16x2: lo elem in low half
        float l0 = x0 - __uint_as_float(b0);
        float l1 = x1 - __uint_as_float(b1);
        __nv_bfloat162 ll = __floats2bfloat162_rn(l0, l1);
        lp[i] = *(uint32_t*)&ll;
    }
    h = make_uint4(hp[0], hp[1], hp[2], hp[3]);
    l = make_uint4(lp[0], lp[1], lp[2], lp[3]);
}

// ---------------------------------------------------------------------------
// GEMM: C[M,N] = A[M,K] @ W[N,K]^T, fp32 in/out, bf16x3 split internally.
//   C = Ahi*Whi + Ahi*Wlo + Alo*Whi   (lo*lo term ~2^-17 rel, dropped)
// M=16384, N=K=512. Block tile 128x128, k-tile 32, 256 threads = 8 warps,
// warp tile 32x64 (2 m16 x 8 n8), mma.m16n8k16, fp32->hi/lo split fused
// into smem staging (same DRAM bytes as reading pre-split bf16).
// smem row stride 40 bf16 (80B) -> ldmatrix conflict-free.
// Register prefetch of next k-tile. Optional fused elu+1 epilogue.
// ---------------------------------------------------------------------------
struct GemmArgs {
    const float* A[3]; const float* W[3]; float* C[3];
    int actmask;
};

__global__ __launch_bounds__(256)
void gemm_bf16x3(GemmArgs args)
{
    const int z = blockIdx.z;
    const float* A = args.A[z];
    const float* W = args.W[z];
    float*       C = args.C[z];
    const bool act = (args.actmask >> z) & 1;

    __shared__ __nv_bfloat16 sAh[128 * 40];
    __shared__ __nv_bfloat16 sAl[128 * 40];
    __shared__ __nv_bfloat16 sBh[128 * 40];
    __shared__ __nv_bfloat16 sBl[128 * 40];

    const int tid  = threadIdx.x;
    const int lane = tid & 31;
    const int warp = tid >> 5;
    const int m0 = blockIdx.y * 128;
    const int n0 = blockIdx.x * 128;
    const int wm0 = (warp & 3) * 32;     // warp row origin in tile
    const int wn0 = (warp >> 2) * 64;    // warp col origin in tile

    // global-load mapping: each thread owns one 16-float row segment
    const int lrow = tid >> 1;           // 0..127
    const int lkc  = (tid & 1) * 16;     // k offset 0 or 16

    const float* gA = A + (size_t)(m0 + lrow) * 512 + lkc;
    const float* gB = W + (size_t)(n0 + lrow) * 512 + lkc;

    float acc[2][8][4];
    #pragma unroll
    for (int i = 0; i < 2; i++)
        #pragma unroll
        for (int j = 0; j < 8; j++)
            #pragma unroll
            for (int t = 0; t < 4; t++) acc[i][j][t] = 0.0f;

    // smem store offsets (bf16 elements); byte offsets are 16B-aligned (80|32)
    const int sA0 = lrow * 40 + lkc;

    // ---- prologue: load k-tile 0 (fp32) ----
    float4 ra[4], rb[4];
    #pragma unroll
    for (int i = 0; i < 4; i++) {
        ra[i] = *(const float4*)(gA + 4 * i);
        rb[i] = *(const float4*)(gB + 4 * i);
    }

    {
        uint4 h0, l0, h1, l1;
        cvt8((const float*)&ra[0], h0, l0);
        cvt8((const float*)&ra[2], h1, l1);
        *(uint4*)&sAh[sA0] = h0; *(uint4*)&sAh[sA0 + 8] = h1;
        *(uint4*)&sAl[sA0] = l0; *(uint4*)&sAl[sA0 + 8] = l1;
        cvt8((const float*)&rb[0], h0, l0);
        cvt8((const float*)&rb[2], h1, l1);
        *(uint4*)&sBh[sA0] = h0; *(uint4*)&sBh[sA0 + 8] = h1;
        *(uint4*)&sBl[sA0] = l0; *(uint4*)&sBl[sA0 + 8] = l1;
    }
    __syncthreads();

    // ldmatrix address components
    const int a_r = lane & 15;              // row within m16 tile
    const int a_c = (lane >> 4) * 8;        // col half
    const int b_r = lane & 7;               // row within n8 tile
    const int b_nt = (lane >> 4) & 1;       // which of 2 n-tiles in x4
    const int b_c = ((lane >> 3) & 1) * 8;  // col half

    for (int kt = 0; kt < 16; ++kt) {
        if (kt < 15) {
            const int ko = (kt + 1) * 32;
            #pragma unroll
            for (int i = 0; i < 4; i++) {
                ra[i] = *(const float4*)(gA + ko + 4 * i);
                rb[i] = *(const float4*)(gB + ko + 4 * i);
            }
        }

        #pragma unroll
        for (int ks = 0; ks < 2; ks++) {
            const int kk = ks * 16;
            unsigned ah[2][4], al[2][4];
            ldsm_x4(ah[0], smem_u32(&sAh[(wm0 + a_r) * 40 + kk + a_c]));
            ldsm_x4(ah[1], smem_u32(&sAh[(wm0 + 16 + a_r) * 40 + kk + a_c]));
            ldsm_x4(al[0], smem_u32(&sAl[(wm0 + a_r) * 40 + kk + a_c]));
            ldsm_x4(al[1], smem_u32(&sAl[(wm0 + 16 + a_r) * 40 + kk + a_c]));

            #pragma unroll
            for (int ntp = 0; ntp < 4; ntp++) {
                unsigned bh[4], bl[4];
                const int brow = wn0 + ntp * 16 + b_nt * 8 + b_r;
                ldsm_x4(bh, smem_u32(&sBh[brow * 40 + kk + b_c]));
                ldsm_x4(bl, smem_u32(&sBl[brow * 40 + kk + b_c]));
                #pragma unroll
                for (int half = 0; half < 2; half++) {
                    const int nt = ntp * 2 + half;
                    const unsigned* bhp = bh + 2 * half;
                    const unsigned* blp = bl + 2 * half;
                    mma_bf16(acc[0][nt], ah[0], bhp);
                    mma_bf16(acc[0][nt], ah[0], blp);
                    mma_bf16(acc[0][nt], al[0], bhp);
                    mma_bf16(acc[1][nt], ah[1], bhp);
                    mma_bf16(acc[1][nt], ah[1], blp);
                    mma_bf16(acc[1][nt], al[1], bhp);
                }
            }
        }

        if (kt < 15) {
            __syncthreads();
            uint4 h0, l0, h1, l1;
            cvt8((const float*)&ra[0], h0, l0);
            cvt8((const float*)&ra[2], h1, l1);
            *(uint4*)&sAh[sA0] = h0; *(uint4*)&sAh[sA0 + 8] = h1;
            *(uint4*)&sAl[sA0] = l0; *(uint4*)&sAl[sA0 + 8] = l1;
            cvt8((const float*)&rb[0], h0, l0);
            cvt8((const float*)&rb[2], h1, l1);
            *(uint4*)&sBh[sA0] = h0; *(uint4*)&sBh[sA0 + 8] = h1;
            *(uint4*)&sBl[sA0] = l0; *(uint4*)&sBl[sA0 + 8] = l1;
            __syncthreads();
        }
    }

    // ---- epilogue: optional elu(x)+1 (= x+1 if x>0 else exp(x)), fp32 out ----
    const int row0 = m0 + wm0 + (lane >> 2);
    const int col0 = n0 + wn0 + (lane & 3) * 2;
    #pragma unroll
    for (int mt = 0; mt < 2; mt++) {
        #pragma unroll
        for (int nt = 0; nt < 8; nt++) {
            float c0 = acc[mt][nt][0], c1 = acc[mt][nt][1];
            float c2 = acc[mt][nt][2], c3 = acc[mt][nt][3];
            if (act) {
                c0 = (c0 > 0.0f) ? (c0 + 1.0f) : expf(c0);
                c1 = (c1 > 0.0f) ? (c1 + 1.0f) : expf(c1);
                c2 = (c2 > 0.0f) ? (c2 + 1.0f) : expf(c2);
                c3 = (c3 > 0.0f) ? (c3 + 1.0f) : expf(c3);
            }
            const int r = row0 + mt * 16;
            const int cc = col0 + nt * 8;
            *(float2*)(C + (size_t)r * 512 + cc)       = make_float2(c0, c1);
            *(float2*)(C + (size_t)(r + 8) * 512 + cc) = make_float2(c2, c3);
        }
    }
}

// ---------------------------------------------------------------------------
// Stage 2a: per-(s-chunk, b, h) partial KV[d][dv] = sum_s K[s,d]*V[s,dv]
// and partial Ksum[d]. Deterministic (no float atomics). NCHUNK=32.
// ---------------------------------------------------------------------------
__global__ void kv_partial(const float* __restrict__ Kf,
                           const float* __restrict__ Vf,
                           float* __restrict__ part)
{
    const int c  = blockIdx.x;
    const int bh = blockIdx.y;
    const int b  = bh >> 4;
    const int h  = bh & 15;
    const int tid = threadIdx.x;

    __shared__ __align__(16) float Ks[8][32];
    __shared__ __align__(16) float Vs[8][32];

    const int d   = tid >> 3;
    const int dv0 = (tid & 7) << 2;
    const int lr  = tid >> 5;   // 0..7
    const int lc  = tid & 31;

    const size_t base = ((size_t)(b * L_ + c * (L_ / NCHUNK)) * 512) + h * 32;
    const float* Kb = Kf + base;
    const float* Vb = Vf + base;

    float a0 = 0.f, a1 = 0.f, a2 = 0.f, a3 = 0.f, ks = 0.f;

    for (int s = 0; s < L_ / NCHUNK; s += 8) {
        Ks[lr][lc] = Kb[(size_t)(s + lr) * 512 + lc];
        Vs[lr][lc] = Vb[(size_t)(s + lr) * 512 + lc];
        __syncthreads();
        #pragma unroll
        for (int u = 0; u < 8; u++) {
            float kd = Ks[u][d];
            float4 vv = *(const float4*)&Vs[u][dv0];
            a0 += kd * vv.x; a1 += kd * vv.y;
            a2 += kd * vv.z; a3 += kd * vv.w;
            ks += kd;
        }
        __syncthreads();
    }

    float* p = part + (size_t)c * PART_STRIDE;
    const int o = bh * 1024 + d * 32 + dv0;
    p[o + 0] = a0; p[o + 1] = a1; p[o + 2] = a2; p[o + 3] = a3;
    if ((tid & 7) == 0) p[KV_ELEMS + bh * 32 + d] = ks;
}

// Stage 2b: reduce NCHUNK partials -> g_KV, g_Ksum (deterministic order)
__global__ void kv_reduce(const float* __restrict__ part,
                          float* __restrict__ KV,
                          float* __restrict__ Ksum)
{
    const int i = blockIdx.x * 256 + threadIdx.x;
    if (i >= PART_STRIDE) return;
    float s = 0.f;
    #pragma unroll
    for (int c = 0; c < NCHUNK; c++) s += part[(size_t)c * PART_STRIDE + i];
    if (i < KV_ELEMS) KV[i] = s;
    else              Ksum[i - KV_ELEMS] = s;
}

// ---------------------------------------------------------------------------
// Stage 3: message. 128 tokens x 1 head per block.
// Z = 1/(Q.Ksum + eps); msg[dv] = Z * sum_d Q[d]*KV[d][dv]
// float4 KV inner loop (4x fewer LDS than scalar version).
// ---------------------------------------------------------------------------
__global__ void msg_kernel(const float* __restrict__ Qf,
                           const float* __restrict__ KV,
                           const float* __restrict__ Ksum,
                           float* __restrict__ Msg)
{
    const int l0 = blockIdx.x * 128;
    const int h  = blockIdx.y;
    const int b  = blockIdx.z;
    const int bh = b * 16 + h;
    const int tid = threadIdx.x;

    __shared__ float Qs[128 * 33];
    __shared__ float Ms[128 * 33];
    __shared__ __align__(16) float KVs[1024];
    __shared__ float ks[32];

    const float* Qb = Qf + ((size_t)(b * L_ + l0) * 512) + h * 32;
    for (int i = tid; i < 128 * 32; i += 128) {
        int l = i >> 5, d = i & 31;
        Qs[l * 33 + d] = Qb[(size_t)l * 512 + d];
    }
    for (int i = tid; i < 1024; i += 128) KVs[i] = KV[(size_t)bh * 1024 + i];
    if (tid < 32) ks[tid] = Ksum[bh * 32 + tid];
    __syncthreads();

    float qr[32];
    #pragma unroll
    for (int d = 0; d < 32; d++) qr[d] = Qs[tid * 33 + d];

    float zden = 0.f;
    #pragma unroll
    for (int d = 0; d < 32; d++) zden += qr[d] * ks[d];
    const float z = 1.0f / (zden + EPS_);

    const float4* KV4 = (const float4*)KVs;
    #pragma unroll
    for (int dq = 0; dq < 8; dq++) {
        float mx = 0.f, my = 0.f, mz = 0.f, mw = 0.f;
        #pragma unroll
        for (int d = 0; d < 32; d++) {
            float4 kv = KV4[d * 8 + dq];
            mx += qr[d] * kv.x; my += qr[d] * kv.y;
            mz += qr[d] * kv.z; mw += qr[d] * kv.w;
        }
        Ms[tid * 33 + dq * 4 + 0] = mx * z;
        Ms[tid * 33 + dq * 4 + 1] = my * z;
        Ms[tid * 33 + dq * 4 + 2] = mz * z;
        Ms[tid * 33 + dq * 4 + 3] = mw * z;
    }
    __syncthreads();

    float* Mb = Msg + ((size_t)(b * L_ + l0) * 512) + h * 32;
    for (int i = tid; i < 128 * 32; i += 128) {
        int l = i >> 5, d = i & 31;
        Mb[(size_t)l * 512 + d] = Ms[l * 33 + d];
    }
}

// ---------------------------------------------------------------------------
// Launch. Inputs (metadata order): query, key, value, Wq, Wk, Wv, Wm. f32 out.
// ---------------------------------------------------------------------------
extern "C" void kernel_launch(void* const* d_in, const int* in_sizes, int n_in,
                              void* d_out, int out_size)
{
    (void)in_sizes; (void)n_in; (void)out_size;
    const float* q  = (const float*)d_in[0];
    const float* k  = (const float*)d_in[1];
    const float* v  = (const float*)d_in[2];
    const float* Wq = (const float*)d_in[3];
    const float* Wk = (const float*)d_in[4];
    const float* Wv = (const float*)d_in[5];
    const float* Wm = (const float*)d_in[6];
    float* out = (float*)d_out;

    float *gQ, *gK, *gV, *gM, *gPart, *gKV, *gKs;
    cudaGetSymbolAddress((void**)&gQ,    g_Q);
    cudaGetSymbolAddress((void**)&gK,    g_K);
    cudaGetSymbolAddress((void**)&gV,    g_V);
    cudaGetSymbolAddress((void**)&gM,    g_M);
    cudaGetSymbolAddress((void**)&gPart, g_part);
    cudaGetSymbolAddress((void**)&gKV,   g_KV);
    cudaGetSymbolAddress((void**)&gKs,   g_Ksum);

    // 1) fused projections (split fused into staging): q,k -> elu+1 ; v -> raw
    {
        GemmArgs a;
        a.A[0] = q; a.W[0] = Wq; a.C[0] = gQ;
        a.A[1] = k; a.W[1] = Wk; a.C[1] = gK;
        a.A[2] = v; a.W[2] = Wv; a.C[2] = gV;
        a.actmask = 0x3;
        gemm_bf16x3<<<dim3(4, 128, 3), 256>>>(a);
    }

    // 2) KV + Ksum (deterministic two-phase reduction)
    kv_partial<<<dim3(NCHUNK, B_ * H_), 256>>>(gK, gV, gPart);
    kv_reduce<<<(PART_STRIDE + 255) / 256, 256>>>(gPart, gKV, gKs);

    // 3) message
    msg_kernel<<<dim3(L_ / 128, H_, B_), 128>>>(gQ, gKV, gKs, gM);

    // 4) output merge projection
    {
        GemmArgs a;
        a.A[0] = gM; a.W[0] = Wm; a.C[0] = out;
        a.A[1] = gM; a.W[1] = Wm; a.C[1] = out;
        a.A[2] = gM; a.W[2] = Wm; a.C[2] = out;
        a.actmask = 0;
        gemm_bf16x3<<<dim3(4, 128, 1), 256>>>(a);
    }
}

// round 8
// speedup vs baseline: 1.8465x; 1.1356x over previous
#include <cuda_runtime.h>
#include <cuda_fp16.h>
#include <math.h>
#include <stdint.h>

// Problem constants
#define B_  4
#define L_  4096
#define E_  512
#define H_  16
#define ML  (B_*L_)            // 16384 tokens
#define EPS_ 1e-6f

// ---------------------------------------------------------------------------
// Scratch (static __device__ arrays; no allocation anywhere)
// ---------------------------------------------------------------------------
__device__ float g_Q[ML*E_];   // elu(q)+1
__device__ float g_K[ML*E_];   // elu(k)+1
__device__ float g_V[ML*E_];   // v projection (unscaled; /L * L cancels exactly)
__device__ float g_M[ML*E_];   // message

#define NCHUNK 32
#define KV_ELEMS   (B_*H_*32*32)     // 65536
#define KSUM_ELEMS (B_*H_*32)        // 2048
#define PART_STRIDE (KV_ELEMS + KSUM_ELEMS)   // 67584
__device__ float g_part[NCHUNK * PART_STRIDE];
__device__ float g_KV[KV_ELEMS];
__device__ float g_Ksum[KSUM_ELEMS];

// ---------------------------------------------------------------------------
// PTX helpers: ldmatrix + fp16 mma (fp32 accumulate)
// ---------------------------------------------------------------------------
__device__ __forceinline__ unsigned smem_u32(const void* p) {
    return (unsigned)__cvta_generic_to_shared(p);
}
__device__ __forceinline__ void ldsm_x4(unsigned* r, unsigned addr) {
    asm volatile("ldmatrix.sync.aligned.m8n8.x4.shared.b16 {%0,%1,%2,%3}, [%4];"
                 : "=r"(r[0]), "=r"(r[1]), "=r"(r[2]), "=r"(r[3]) : "r"(addr));
}
__device__ __forceinline__ void mma_f16(float* c, const unsigned* a, const unsigned* b) {
    asm volatile("mma.sync.aligned.m16n8k16.row.col.f32.f16.f16.f32 "
                 "{%0,%1,%2,%3}, {%4,%5,%6,%7}, {%8,%9}, {%0,%1,%2,%3};"
                 : "+f"(c[0]), "+f"(c[1]), "+f"(c[2]), "+f"(c[3])
                 : "r"(a[0]), "r"(a[1]), "r"(a[2]), "r"(a[3]),
                   "r"(b[0]), "r"(b[1]));
}

// ---------------------------------------------------------------------------
// 8 fp32 -> fp16 hi (rn) + fp16 lo (exact residual, rn). hi+lo captures ~22
// mantissa bits; residual ~2^-22 relative.
// ---------------------------------------------------------------------------
__device__ __forceinline__ void cvt8_split(const float* __restrict__ v8,
                                           uint4& h, uint4& l) {
    uint32_t hp[4], lp[4];
    #pragma unroll
    for (int i = 0; i < 4; i++) {
        float x0 = v8[2*i], x1 = v8[2*i+1];
        __half2 hh = __floats2half2_rn(x0, x1);
        float2 hf = __half22float2(hh);
        __half2 ll = __floats2half2_rn(x0 - hf.x, x1 - hf.y);
        hp[i] = *(uint32_t*)&hh;
        lp[i] = *(uint32_t*)&ll;
    }
    h = make_uint4(hp[0], hp[1], hp[2], hp[3]);
    l = make_uint4(lp[0], lp[1], lp[2], lp[3]);
}
// 8 fp32 -> single fp16 (rn); quantization ~2^-12 relative (the error budget)
__device__ __forceinline__ void cvt8_h(const float* __restrict__ v8, uint4& h) {
    uint32_t hp[4];
    #pragma unroll
    for (int i = 0; i < 4; i++) {
        __half2 hh = __floats2half2_rn(v8[2*i], v8[2*i+1]);
        hp[i] = *(uint32_t*)&hh;
    }
    h = make_uint4(hp[0], hp[1], hp[2], hp[3]);
}

// ---------------------------------------------------------------------------
// GEMM: C[M,N] = A[M,K] @ W[N,K]^T, fp32 in/out, fp16x2 split internally.
//   C = Ahi*W + Alo*W     (A to ~22 bits; W single fp16 ~2^-12 rel err)
// 2 mma terms (was 3 with bf16x3) -> 2/3 tensor-pipe work, half the B-side
// ldmatrix traffic. Tiling/addressing identical to the proven R7 kernel:
// block 128x128, k-tile 32, 8 warps, warp tile 32x64, mma.m16n8k16,
// smem row stride 40 halves -> ldmatrix conflict-free, register prefetch.
// ---------------------------------------------------------------------------
struct GemmArgs {
    const float* A[3]; const float* W[3]; float* C[3];
    int actmask;
};

__global__ __launch_bounds__(256)
void gemm_f16x2(GemmArgs args)
{
    const int z = blockIdx.z;
    const float* A = args.A[z];
    const float* W = args.W[z];
    float*       C = args.C[z];
    const bool act = (args.actmask >> z) & 1;

    __shared__ __half sAh[128 * 40];
    __shared__ __half sAl[128 * 40];
    __shared__ __half sB [128 * 40];

    const int tid  = threadIdx.x;
    const int lane = tid & 31;
    const int warp = tid >> 5;
    const int m0 = blockIdx.y * 128;
    const int n0 = blockIdx.x * 128;
    const int wm0 = (warp & 3) * 32;     // warp row origin in tile
    const int wn0 = (warp >> 2) * 64;    // warp col origin in tile

    // global-load mapping: each thread owns one 16-float row segment
    const int lrow = tid >> 1;           // 0..127
    const int lkc  = (tid & 1) * 16;     // k offset 0 or 16

    const float* gA = A + (size_t)(m0 + lrow) * 512 + lkc;
    const float* gB = W + (size_t)(n0 + lrow) * 512 + lkc;

    float acc[2][8][4];
    #pragma unroll
    for (int i = 0; i < 2; i++)
        #pragma unroll
        for (int j = 0; j < 8; j++)
            #pragma unroll
            for (int t = 0; t < 4; t++) acc[i][j][t] = 0.0f;

    const int sA0 = lrow * 40 + lkc;

    // ---- prologue: load k-tile 0 (fp32) ----
    float4 ra[4], rb[4];
    #pragma unroll
    for (int i = 0; i < 4; i++) {
        ra[i] = *(const float4*)(gA + 4 * i);
        rb[i] = *(const float4*)(gB + 4 * i);
    }
    {
        uint4 h0, l0, h1, l1;
        cvt8_split((const float*)&ra[0], h0, l0);
        cvt8_split((const float*)&ra[2], h1, l1);
        *(uint4*)&sAh[sA0] = h0; *(uint4*)&sAh[sA0 + 8] = h1;
        *(uint4*)&sAl[sA0] = l0; *(uint4*)&sAl[sA0 + 8] = l1;
        cvt8_h((const float*)&rb[0], h0);
        cvt8_h((const float*)&rb[2], h1);
        *(uint4*)&sB[sA0] = h0; *(uint4*)&sB[sA0 + 8] = h1;
    }
    __syncthreads();

    // ldmatrix address components
    const int a_r = lane & 15;              // row within m16 tile
    const int a_c = (lane >> 4) * 8;        // col half
    const int b_r = lane & 7;               // row within n8 tile
    const int b_nt = (lane >> 4) & 1;       // which of 2 n-tiles in x4
    const int b_c = ((lane >> 3) & 1) * 8;  // col half

    for (int kt = 0; kt < 16; ++kt) {
        if (kt < 15) {
            const int ko = (kt + 1) * 32;
            #pragma unroll
            for (int i = 0; i < 4; i++) {
                ra[i] = *(const float4*)(gA + ko + 4 * i);
                rb[i] = *(const float4*)(gB + ko + 4 * i);
            }
        }

        #pragma unroll
        for (int ks = 0; ks < 2; ks++) {
            const int kk = ks * 16;
            unsigned ah[2][4], al[2][4];
            ldsm_x4(ah[0], smem_u32(&sAh[(wm0 + a_r) * 40 + kk + a_c]));
            ldsm_x4(ah[1], smem_u32(&sAh[(wm0 + 16 + a_r) * 40 + kk + a_c]));
            ldsm_x4(al[0], smem_u32(&sAl[(wm0 + a_r) * 40 + kk + a_c]));
            ldsm_x4(al[1], smem_u32(&sAl[(wm0 + 16 + a_r) * 40 + kk + a_c]));

            #pragma unroll
            for (int ntp = 0; ntp < 4; ntp++) {
                unsigned b[4];
                const int brow = wn0 + ntp * 16 + b_nt * 8 + b_r;
                ldsm_x4(b, smem_u32(&sB[brow * 40 + kk + b_c]));
                #pragma unroll
                for (int half = 0; half < 2; half++) {
                    const int nt = ntp * 2 + half;
                    const unsigned* bp = b + 2 * half;
                    mma_f16(acc[0][nt], ah[0], bp);
                    mma_f16(acc[0][nt], al[0], bp);
                    mma_f16(acc[1][nt], ah[1], bp);
                    mma_f16(acc[1][nt], al[1], bp);
                }
            }
        }

        if (kt < 15) {
            __syncthreads();
            uint4 h0, l0, h1, l1;
            cvt8_split((const float*)&ra[0], h0, l0);
            cvt8_split((const float*)&ra[2], h1, l1);
            *(uint4*)&sAh[sA0] = h0; *(uint4*)&sAh[sA0 + 8] = h1;
            *(uint4*)&sAl[sA0] = l0; *(uint4*)&sAl[sA0 + 8] = l1;
            cvt8_h((const float*)&rb[0], h0);
            cvt8_h((const float*)&rb[2], h1);
            *(uint4*)&sB[sA0] = h0; *(uint4*)&sB[sA0 + 8] = h1;
            __syncthreads();
        }
    }

    // ---- epilogue: optional elu(x)+1 (= x+1 if x>0 else exp(x)), fp32 out ----
    const int row0 = m0 + wm0 + (lane >> 2);
    const int col0 = n0 + wn0 + (lane & 3) * 2;
    #pragma unroll
    for (int mt = 0; mt < 2; mt++) {
        #pragma unroll
        for (int nt = 0; nt < 8; nt++) {
            float c0 = acc[mt][nt][0], c1 = acc[mt][nt][1];
            float c2 = acc[mt][nt][2], c3 = acc[mt][nt][3];
            if (act) {
                c0 = (c0 > 0.0f) ? (c0 + 1.0f) : expf(c0);
                c1 = (c1 > 0.0f) ? (c1 + 1.0f) : expf(c1);
                c2 = (c2 > 0.0f) ? (c2 + 1.0f) : expf(c2);
                c3 = (c3 > 0.0f) ? (c3 + 1.0f) : expf(c3);
            }
            const int r = row0 + mt * 16;
            const int cc = col0 + nt * 8;
            *(float2*)(C + (size_t)r * 512 + cc)       = make_float2(c0, c1);
            *(float2*)(C + (size_t)(r + 8) * 512 + cc) = make_float2(c2, c3);
        }
    }
}

// ---------------------------------------------------------------------------
// Stage 2a: per-(s-chunk, b, h) partial KV[d][dv] = sum_s K[s,d]*V[s,dv]
// and partial Ksum[d]. Deterministic (no float atomics). NCHUNK=32.
// ---------------------------------------------------------------------------
__global__ void kv_partial(const float* __restrict__ Kf,
                           const float* __restrict__ Vf,
                           float* __restrict__ part)
{
    const int c  = blockIdx.x;
    const int bh = blockIdx.y;
    const int b  = bh >> 4;
    const int h  = bh & 15;
    const int tid = threadIdx.x;

    __shared__ __align__(16) float Ks[8][32];
    __shared__ __align__(16) float Vs[8][32];

    const int d   = tid >> 3;
    const int dv0 = (tid & 7) << 2;
    const int lr  = tid >> 5;   // 0..7
    const int lc  = tid & 31;

    const size_t base = ((size_t)(b * L_ + c * (L_ / NCHUNK)) * 512) + h * 32;
    const float* Kb = Kf + base;
    const float* Vb = Vf + base;

    float a0 = 0.f, a1 = 0.f, a2 = 0.f, a3 = 0.f, ks = 0.f;

    for (int s = 0; s < L_ / NCHUNK; s += 8) {
        Ks[lr][lc] = Kb[(size_t)(s + lr) * 512 + lc];
        Vs[lr][lc] = Vb[(size_t)(s + lr) * 512 + lc];
        __syncthreads();
        #pragma unroll
        for (int u = 0; u < 8; u++) {
            float kd = Ks[u][d];
            float4 vv = *(const float4*)&Vs[u][dv0];
            a0 += kd * vv.x; a1 += kd * vv.y;
            a2 += kd * vv.z; a3 += kd * vv.w;
            ks += kd;
        }
        __syncthreads();
    }

    float* p = part + (size_t)c * PART_STRIDE;
    const int o = bh * 1024 + d * 32 + dv0;
    p[o + 0] = a0; p[o + 1] = a1; p[o + 2] = a2; p[o + 3] = a3;
    if ((tid & 7) == 0) p[KV_ELEMS + bh * 32 + d] = ks;
}

// Stage 2b: reduce NCHUNK partials -> g_KV, g_Ksum (deterministic order)
__global__ void kv_reduce(const float* __restrict__ part,
                          float* __restrict__ KV,
                          float* __restrict__ Ksum)
{
    const int i = blockIdx.x * 256 + threadIdx.x;
    if (i >= PART_STRIDE) return;
    float s = 0.f;
    #pragma unroll
    for (int c = 0; c < NCHUNK; c++) s += part[(size_t)c * PART_STRIDE + i];
    if (i < KV_ELEMS) KV[i] = s;
    else              Ksum[i - KV_ELEMS] = s;
}

// ---------------------------------------------------------------------------
// Stage 3: message. 128 tokens x 1 head per block.
// Z = 1/(Q.Ksum + eps); msg[dv] = Z * sum_d Q[d]*KV[d][dv]
// ---------------------------------------------------------------------------
__global__ void msg_kernel(const float* __restrict__ Qf,
                           const float* __restrict__ KV,
                           const float* __restrict__ Ksum,
                           float* __restrict__ Msg)
{
    const int l0 = blockIdx.x * 128;
    const int h  = blockIdx.y;
    const int b  = blockIdx.z;
    const int bh = b * 16 + h;
    const int tid = threadIdx.x;

    __shared__ float Qs[128 * 33];
    __shared__ float Ms[128 * 33];
    __shared__ __align__(16) float KVs[1024];
    __shared__ float ks[32];

    const float* Qb = Qf + ((size_t)(b * L_ + l0) * 512) + h * 32;
    for (int i = tid; i < 128 * 32; i += 128) {
        int l = i >> 5, d = i & 31;
        Qs[l * 33 + d] = Qb[(size_t)l * 512 + d];
    }
    for (int i = tid; i < 1024; i += 128) KVs[i] = KV[(size_t)bh * 1024 + i];
    if (tid < 32) ks[tid] = Ksum[bh * 32 + tid];
    __syncthreads();

    float qr[32];
    #pragma unroll
    for (int d = 0; d < 32; d++) qr[d] = Qs[tid * 33 + d];

    float zden = 0.f;
    #pragma unroll
    for (int d = 0; d < 32; d++) zden += qr[d] * ks[d];
    const float z = 1.0f / (zden + EPS_);

    const float4* KV4 = (const float4*)KVs;
    #pragma unroll
    for (int dq = 0; dq < 8; dq++) {
        float mx = 0.f, my = 0.f, mz = 0.f, mw = 0.f;
        #pragma unroll
        for (int d = 0; d < 32; d++) {
            float4 kv = KV4[d * 8 + dq];
            mx += qr[d] * kv.x; my += qr[d] * kv.y;
            mz += qr[d] * kv.z; mw += qr[d] * kv.w;
        }
        Ms[tid * 33 + dq * 4 + 0] = mx * z;
        Ms[tid * 33 + dq * 4 + 1] = my * z;
        Ms[tid * 33 + dq * 4 + 2] = mz * z;
        Ms[tid * 33 + dq * 4 + 3] = mw * z;
    }
    __syncthreads();

    float* Mb = Msg + ((size_t)(b * L_ + l0) * 512) + h * 32;
    for (int i = tid; i < 128 * 32; i += 128) {
        int l = i >> 5, d = i & 31;
        Mb[(size_t)l * 512 + d] = Ms[l * 33 + d];
    }
}

// ---------------------------------------------------------------------------
// Launch. Inputs (metadata order): query, key, value, Wq, Wk, Wv, Wm. f32 out.
// ---------------------------------------------------------------------------
extern "C" void kernel_launch(void* const* d_in, const int* in_sizes, int n_in,
                              void* d_out, int out_size)
{
    (void)in_sizes; (void)n_in; (void)out_size;
    const float* q  = (const float*)d_in[0];
    const float* k  = (const float*)d_in[1];
    const float* v  = (const float*)d_in[2];
    const float* Wq = (const float*)d_in[3];
    const float* Wk = (const float*)d_in[4];
    const float* Wv = (const float*)d_in[5];
    const float* Wm = (const float*)d_in[6];
    float* out = (float*)d_out;

    float *gQ, *gK, *gV, *gM, *gPart, *gKV, *gKs;
    cudaGetSymbolAddress((void**)&gQ,    g_Q);
    cudaGetSymbolAddress((void**)&gK,    g_K);
    cudaGetSymbolAddress((void**)&gV,    g_V);
    cudaGetSymbolAddress((void**)&gM,    g_M);
    cudaGetSymbolAddress((void**)&gPart, g_part);
    cudaGetSymbolAddress((void**)&gKV,   g_KV);
    cudaGetSymbolAddress((void**)&gKs,   g_Ksum);

    // 1) fused projections (fp16x2 split in staging): q,k -> elu+1 ; v -> raw
    {
        GemmArgs a;
        a.A[0] = q; a.W[0] = Wq; a.C[0] = gQ;
        a.A[1] = k; a.W[1] = Wk; a.C[1] = gK;
        a.A[2] = v; a.W[2] = Wv; a.C[2] = gV;
        a.actmask = 0x3;
        gemm_f16x2<<<dim3(4, 128, 3), 256>>>(a);
    }

    // 2) KV + Ksum (deterministic two-phase reduction)
    kv_partial<<<dim3(NCHUNK, B_ * H_), 256>>>(gK, gV, gPart);
    kv_reduce<<<(PART_STRIDE + 255) / 256, 256>>>(gPart, gKV, gKs);

    // 3) message
    msg_kernel<<<dim3(L_ / 128, H_, B_), 128>>>(gQ, gKV, gKs, gM);

    // 4) output merge projection
    {
        GemmArgs a;
        a.A[0] = gM; a.W[0] = Wm; a.C[0] = out;
        a.A[1] = gM; a.W[1] = Wm; a.C[1] = out;
        a.A[2] = gM; a.W[2] = Wm; a.C[2] = out;
        a.actmask = 0;
        gemm_f16x2<<<dim3(4, 128, 1), 256>>>(a);
    }
}